// round 15
// baseline (speedup 1.0000x reference)
#include <cuda_runtime.h>

typedef unsigned long long u64;

__device__ __forceinline__ u64 pk2(float lo, float hi) {
    u64 r; asm("mov.b64 %0,{%1,%2};" : "=l"(r) : "f"(lo), "f"(hi)); return r;
}
__device__ __forceinline__ float2 up2(u64 v) {
    float2 f; asm("mov.b64 {%0,%1},%2;" : "=f"(f.x), "=f"(f.y) : "l"(v)); return f;
}
__device__ __forceinline__ u64 fma2(u64 a, u64 b, u64 c) {
    u64 d; asm("fma.rn.f32x2 %0,%1,%2,%3;" : "=l"(d) : "l"(a), "l"(b), "l"(c)); return d;
}
__device__ __forceinline__ u64 add2(u64 a, u64 b) {
    u64 d; asm("add.rn.f32x2 %0,%1,%2;" : "=l"(d) : "l"(a), "l"(b)); return d;
}
__device__ __forceinline__ u64 clamp2(u64 v) {
    float2 f = up2(v);
    f.x = fminf(fmaxf(f.x, -1.0f), 1.0f);
    f.y = fminf(fmaxf(f.y, -1.0f), 1.0f);
    return pk2(f.x, f.y);
}
__device__ __forceinline__ u64 shfl_xor64(u64 v) {
    return (u64)__shfl_xor_sync(0xffffffffu, (unsigned long long)v, 1);
}

#define NPMAX 65536
// transposed input, interleaved col-pairs: pair cp, sample-pair t ->
//   ulonglong2{ pack(col 2cp, t), pack(col 2cp+1, t) }   (193 col-pairs)
__device__ u64 g_T2[(size_t)2 * 193 * NPMAX];   // 202 MB
// sight scratch: ulonglong2 row r (0..143): {sight[2r] pair, sight[2r+1] pair}
__device__ u64 g_S[(size_t)144 * NPMAX];        // 75.5 MB

// ------------------------- transpose + pack kernel -------------------------
__global__ void transpose_kernel(const float* __restrict__ inp, int np)
{
    __shared__ float tile[64][33];
    int bx = blockIdx.x;            // col tile (0..12): cols bx*32..bx*32+31
    int by = blockIdx.y;            // 64-sample tile
    int tid = threadIdx.x;
    int lx = tid & 31, ly = tid >> 5;
    int col = bx * 32 + lx;

    #pragma unroll
    for (int i = 0; i < 8; i++) {
        int r = ly + i * 8;
        float v = 0.0f;
        if (col < 385) v = inp[(size_t)(by * 64 + r) * 385 + col];
        tile[r][lx] = v;
    }
    __syncthreads();

    int pl = tid & 31;              // sample-pair within tile (0..31)
    int cl = tid >> 5;              // 0..7
    ulonglong2* T2 = reinterpret_cast<ulonglong2*>(g_T2);
    #pragma unroll
    for (int i = 0; i < 2; i++) {
        int cpl = cl + i * 8;       // local col-pair (0..15)
        int c   = cpl * 2;
        int gcp = bx * 16 + cpl;    // global col-pair
        if (gcp < 193) {
            u64 lo = pk2(tile[2 * pl][c],     tile[2 * pl + 1][c]);
            u64 hi = pk2(tile[2 * pl][c + 1], tile[2 * pl + 1][c + 1]);
            T2[(size_t)gcp * np + by * 32 + pl] = make_ulonglong2(lo, hi);
        }
    }
}

// ------------------------------ conv kernel -------------------------------
// Thread pairs (2u, 2u+1) share sample-pair t=u; p=tid&1 selects neuron half
// (L1 neurons 6p..6p+5) and, after the shuffle exchange, the window (A/B).
#define A_W1 0      // 648
#define A_B1 648    // 12
#define A_W2 660    // 144
#define A_B2 804    // 12
#define A_W3 816    // 48
#define A_B3 864    // 4
#define A_N  868

__global__ void __launch_bounds__(128, 6) conv_kernel(
    const float* __restrict__ W1, const float* __restrict__ b1,
    const float* __restrict__ W2, const float* __restrict__ b2,
    const float* __restrict__ W3, const float* __restrict__ b3,
    int np)
{
    __shared__ __align__(16) u64 sw[A_N];
    int tid = threadIdx.x;
    for (int i = tid; i < 648; i += 128) { float v = W1[i]; sw[A_W1+i] = pk2(v,v); }
    for (int i = tid; i < 12;  i += 128) { sw[A_B1+i] = pk2(b1[i],b1[i]);
                                           sw[A_B2+i] = pk2(b2[i],b2[i]); }
    for (int i = tid; i < 144; i += 128) { sw[A_W2+i] = pk2(W2[i],W2[i]); }
    for (int i = tid; i < 48;  i += 128) { sw[A_W3+i] = pk2(W3[i],W3[i]); }
    if (tid < 4) sw[A_B3+tid] = pk2(b3[tid],b3[tid]);
    __syncthreads();

    int gtid = blockIdx.x * 128 + tid;
    int t = gtid >> 1;
    int p = gtid & 1;
    if (t >= np) return;
    int np6 = 6 * p;                 // neuron offset for L1

    const ulonglong2* T2 = reinterpret_cast<const ulonglong2*>(g_T2);
    ulonglong2* S = reinterpret_cast<ulonglong2*>(g_S);

    #pragma unroll 1
    for (int wp = 0; wp < 18; wp++) {
        int x  = wp / 3;
        int yy = (wp - x * 3) * 2;
        int cpb = x * 24 + yy * 3;   // col-pair base

        // L1: 6 neurons (np6..np6+5) for both windows of the pair
        u64 ha[6], hb[6];
        #pragma unroll
        for (int n = 0; n < 6; n++) { ha[n] = sw[A_B1 + np6 + n]; hb[n] = ha[n]; }

        #pragma unroll 1
        for (int ox = 0; ox < 3; ox++) {
            const ulonglong2* g = T2 + (size_t)(cpb + ox * 24) * np + t;
            const u64* wk = sw + A_W1 + ox * 216 + np6;

            // rolling 12-col packed buffer; 6+3+3 LDG.128 per ox
            u64 v[12];
            #pragma unroll
            for (int i = 0; i < 6; i++) {
                ulonglong2 a = __ldg(g + (size_t)i * np);
                v[2*i] = a.x; v[2*i+1] = a.y;
            }
            #pragma unroll
            for (int kk = 0; kk < 6; kk++) {
                u64 va = v[kk], vb = v[kk + 6];
                const ulonglong2* w2 = reinterpret_cast<const ulonglong2*>(wk + kk * 12);
                #pragma unroll
                for (int n2 = 0; n2 < 3; n2++) {
                    ulonglong2 w = w2[n2];
                    ha[2*n2]   = fma2(va, w.x, ha[2*n2]);
                    ha[2*n2+1] = fma2(va, w.y, ha[2*n2+1]);
                    hb[2*n2]   = fma2(vb, w.x, hb[2*n2]);
                    hb[2*n2+1] = fma2(vb, w.y, hb[2*n2+1]);
                }
            }
            #pragma unroll
            for (int i = 0; i < 6; i++) v[i] = v[i + 6];
            #pragma unroll
            for (int i = 0; i < 3; i++) {
                ulonglong2 a = __ldg(g + (size_t)(6 + i) * np);
                v[6+2*i] = a.x; v[7+2*i] = a.y;
            }
            #pragma unroll
            for (int kk = 0; kk < 6; kk++) {
                u64 va = v[kk], vb = v[kk + 6];
                const ulonglong2* w2 = reinterpret_cast<const ulonglong2*>(wk + (6 + kk) * 12);
                #pragma unroll
                for (int n2 = 0; n2 < 3; n2++) {
                    ulonglong2 w = w2[n2];
                    ha[2*n2]   = fma2(va, w.x, ha[2*n2]);
                    ha[2*n2+1] = fma2(va, w.y, ha[2*n2+1]);
                    hb[2*n2]   = fma2(vb, w.x, hb[2*n2]);
                    hb[2*n2+1] = fma2(vb, w.y, hb[2*n2+1]);
                }
            }
            #pragma unroll
            for (int i = 0; i < 6; i++) v[i] = v[i + 6];
            #pragma unroll
            for (int i = 0; i < 3; i++) {
                ulonglong2 a = __ldg(g + (size_t)(9 + i) * np);
                v[6+2*i] = a.x; v[7+2*i] = a.y;
            }
            #pragma unroll
            for (int kk = 0; kk < 6; kk++) {
                u64 va = v[kk], vb = v[kk + 6];
                const ulonglong2* w2 = reinterpret_cast<const ulonglong2*>(wk + (12 + kk) * 12);
                #pragma unroll
                for (int n2 = 0; n2 < 3; n2++) {
                    ulonglong2 w = w2[n2];
                    ha[2*n2]   = fma2(va, w.x, ha[2*n2]);
                    ha[2*n2+1] = fma2(va, w.y, ha[2*n2+1]);
                    hb[2*n2]   = fma2(vb, w.x, hb[2*n2]);
                    hb[2*n2+1] = fma2(vb, w.y, hb[2*n2+1]);
                }
            }
        }
        #pragma unroll
        for (int n = 0; n < 6; n++) { ha[n] = clamp2(ha[n]); hb[n] = clamp2(hb[n]); }

        // exchange: even ends with full winA h[12], odd with full winB h[12]
        u64 h[12];
        #pragma unroll
        for (int i = 0; i < 6; i++) {
            u64 snd = p ? ha[i] : hb[i];
            u64 rcv = shfl_xor64(snd);
            h[i]     = p ? rcv  : ha[i];
            h[6 + i] = p ? hb[i] : rcv;
        }

        // layer 2: 12 -> 12 (one window per thread)
        u64 gg[12];
        #pragma unroll
        for (int n = 0; n < 12; n++) gg[n] = sw[A_B2 + n];
        #pragma unroll 4
        for (int k = 0; k < 12; k++) {
            const ulonglong2* w2 = reinterpret_cast<const ulonglong2*>(sw + A_W2 + k * 12);
            #pragma unroll
            for (int n2 = 0; n2 < 6; n2++) {
                ulonglong2 w = w2[n2];
                gg[2*n2]   = fma2(h[k], w.x, gg[2*n2]);
                gg[2*n2+1] = fma2(h[k], w.y, gg[2*n2+1]);
            }
        }
        #pragma unroll
        for (int n = 0; n < 12; n++) gg[n] = clamp2(gg[n]);

        // layer 3: 12 -> 4
        u64 s[4];
        #pragma unroll
        for (int q = 0; q < 4; q++) s[q] = sw[A_B3 + q];
        #pragma unroll
        for (int k = 0; k < 12; k++) {
            const ulonglong2* w2 = reinterpret_cast<const ulonglong2*>(sw + A_W3 + k * 4);
            ulonglong2 w0 = w2[0];
            ulonglong2 w1 = w2[1];
            s[0] = fma2(gg[k], w0.x, s[0]);
            s[1] = fma2(gg[k], w0.y, s[1]);
            s[2] = fma2(gg[k], w1.x, s[2]);
            s[3] = fma2(gg[k], w1.y, s[3]);
        }
        #pragma unroll
        for (int q = 0; q < 4; q++) s[q] = clamp2(s[q]);

        // store: window index = wa + p; its rows are 2*(wa+p), 2*(wa+p)+1
        int wa = x * 6 + yy;
        size_t rb = (size_t)(2 * (wa + p)) * np + t;
        S[rb]      = make_ulonglong2(s[0], s[1]);
        S[rb + np] = make_ulonglong2(s[2], s[3]);
    }
}

// ------------------------------ head kernel -------------------------------
#define H_V1 0      // 4640 (145x32 dup pairs)
#define H_C1 4640   // 32
#define H_C2 4672   // 32
#define H_V3 4704   // 32
#define H_V2 4736   // 1024 (V2 transposed dup pairs: [j][k])
#define H_C3 5760   // 1 (+1 pad)
#define H_N  5762   // 46096 B

__global__ void __launch_bounds__(128, 5) head_kernel(
    const float* __restrict__ V1, const float* __restrict__ c1,
    const float* __restrict__ V2, const float* __restrict__ c2,
    const float* __restrict__ V3, const float* __restrict__ c3,
    float* __restrict__ out, int np)
{
    __shared__ __align__(16) u64 sv[H_N];
    int tid = threadIdx.x;
    for (int i = tid; i < 4640; i += 128) { float v = V1[i]; sv[H_V1+i] = pk2(v,v); }
    for (int i = tid; i < 32;   i += 128) { sv[H_C1+i] = pk2(c1[i],c1[i]);
                                            sv[H_C2+i] = pk2(c2[i],c2[i]);
                                            sv[H_V3+i] = pk2(V3[i],V3[i]); }
    for (int i = tid; i < 1024; i += 128) { int j = i >> 5, k = i & 31;
                                            float v = V2[k*32 + j]; sv[H_V2+i] = pk2(v,v); }
    if (tid == 0) sv[H_C3] = pk2(c3[0], c3[0]);
    __syncthreads();

    int t = blockIdx.x * 128 + tid;
    if (t >= np) return;

    const ulonglong2* S = reinterpret_cast<const ulonglong2*>(g_S);

    u64 acc[32];
    #pragma unroll
    for (int j = 0; j < 32; j++) acc[j] = 0ull;

    #pragma unroll 2
    for (int cp = 0; cp < 72; cp++) {
        ulonglong2 s = __ldg(S + (size_t)cp * np + t);
        const ulonglong2* wk0 = reinterpret_cast<const ulonglong2*>(sv + H_V1 + (2*cp)   * 32);
        const ulonglong2* wk1 = reinterpret_cast<const ulonglong2*>(sv + H_V1 + (2*cp+1) * 32);
        #pragma unroll
        for (int j2 = 0; j2 < 16; j2++) {
            ulonglong2 wA = wk0[j2];
            ulonglong2 wB = wk1[j2];
            acc[2*j2]   = fma2(s.x, wA.x, acc[2*j2]);
            acc[2*j2]   = fma2(s.y, wB.x, acc[2*j2]);
            acc[2*j2+1] = fma2(s.x, wA.y, acc[2*j2+1]);
            acc[2*j2+1] = fma2(s.y, wB.y, acc[2*j2+1]);
        }
    }

    // vision[144] = inp[:,384] (col-pair 192, low element)
    u64 last = g_T2[((size_t)192 * np + t) * 2];
    const u64* v1l = sv + H_V1 + 144 * 32;
    #pragma unroll
    for (int j = 0; j < 32; j++) {
        acc[j] = clamp2(add2(fma2(last, v1l[j], acc[j]), sv[H_C1 + j]));
    }

    // V2 (32->32) + V3 (32->1) fused; V2 stored transposed dup'd pairs
    u64 o = sv[H_C3];
    #pragma unroll 1
    for (int j = 0; j < 32; j++) {
        u64 e = sv[H_C2 + j];
        const ulonglong2* w2 = reinterpret_cast<const ulonglong2*>(sv + H_V2 + j * 32);
        #pragma unroll
        for (int k2 = 0; k2 < 16; k2++) {
            ulonglong2 w = w2[k2];
            e = fma2(acc[2*k2],   w.x, e);
            e = fma2(acc[2*k2+1], w.y, e);
        }
        e = clamp2(e);
        o = fma2(e, sv[H_V3 + j], o);
    }
    o = clamp2(o);

    reinterpret_cast<float2*>(out)[t] = up2(o);
}

extern "C" void kernel_launch(void* const* d_in, const int* in_sizes, int n_in,
                              void* d_out, int out_size) {
    const float* inp = (const float*)d_in[0];
    const float* W1  = (const float*)d_in[1];
    const float* b1  = (const float*)d_in[2];
    const float* W2  = (const float*)d_in[3];
    const float* b2  = (const float*)d_in[4];
    const float* W3  = (const float*)d_in[5];
    const float* b3  = (const float*)d_in[6];
    const float* V1  = (const float*)d_in[7];
    const float* c1  = (const float*)d_in[8];
    const float* V2  = (const float*)d_in[9];
    const float* c2  = (const float*)d_in[10];
    const float* V3  = (const float*)d_in[11];
    const float* c3  = (const float*)d_in[12];

    int B  = in_sizes[0] / 385;   // 131072
    int np = B / 2;               // 65536 sample-pairs

    dim3 tgrid(13, B / 64);
    transpose_kernel<<<tgrid, 256>>>(inp, np);

    int cblocks = (2 * np + 127) / 128;   // 2 threads per sample-pair
    conv_kernel<<<cblocks, 128>>>(W1, b1, W2, b2, W3, b3, np);

    int hblocks = (np + 127) / 128;
    head_kernel<<<hblocks, 128>>>(V1, c1, V2, c2, V3, c3, (float*)d_out, np);
}

// round 16
// speedup vs baseline: 1.1165x; 1.1165x over previous
#include <cuda_runtime.h>
#include <cuda_fp16.h>

typedef unsigned long long u64;

__device__ __forceinline__ u64 pk2(float lo, float hi) {
    u64 r; asm("mov.b64 %0,{%1,%2};" : "=l"(r) : "f"(lo), "f"(hi)); return r;
}
__device__ __forceinline__ float2 up2(u64 v) {
    float2 f; asm("mov.b64 {%0,%1},%2;" : "=f"(f.x), "=f"(f.y) : "l"(v)); return f;
}
__device__ __forceinline__ u64 fma2(u64 a, u64 b, u64 c) {
    u64 d; asm("fma.rn.f32x2 %0,%1,%2,%3;" : "=l"(d) : "l"(a), "l"(b), "l"(c)); return d;
}
__device__ __forceinline__ u64 add2(u64 a, u64 b) {
    u64 d; asm("add.rn.f32x2 %0,%1,%2;" : "=l"(d) : "l"(a), "l"(b)); return d;
}
__device__ __forceinline__ u64 clamp2(u64 v) {
    float2 f = up2(v);
    f.x = fminf(fmaxf(f.x, -1.0f), 1.0f);
    f.y = fminf(fmaxf(f.y, -1.0f), 1.0f);
    return pk2(f.x, f.y);
}
__device__ __forceinline__ u64 shfl_xor64(u64 v) {
    return (u64)__shfl_xor_sync(0xffffffffu, (unsigned long long)v, 1);
}
// u64 packed float pair -> half2 bits (uint)
__device__ __forceinline__ unsigned int pair_to_h2(u64 v) {
    float2 f = up2(v);
    __half2 h = __float22half2_rn(f);
    return *reinterpret_cast<unsigned int*>(&h);
}
// half2 bits -> u64 packed float pair
__device__ __forceinline__ u64 h2_to_pair(unsigned int b) {
    __half2 h = *reinterpret_cast<__half2*>(&b);
    float2 f = __half22float2(h);
    return pk2(f.x, f.y);
}

#define NPMAX 65536
// transposed input, interleaved col-pairs: pair cp, sample-pair t ->
//   ulonglong2{ pack(col 2cp, t), pack(col 2cp+1, t) }   (193 col-pairs)
__device__ u64 g_T2[(size_t)2 * 193 * NPMAX];   // 202 MB
// sight scratch (fp16): window w (0..35), sample-pair t ->
//   uint4{ h2(sight[4w]), h2(sight[4w+1]), h2(sight[4w+2]), h2(sight[4w+3]) }
__device__ uint4 g_Sh[(size_t)36 * NPMAX];      // 37.7 MB

// ------------------------- transpose + pack kernel -------------------------
__global__ void transpose_kernel(const float* __restrict__ inp, int np)
{
    __shared__ float tile[64][33];
    int bx = blockIdx.x;            // col tile (0..12): cols bx*32..bx*32+31
    int by = blockIdx.y;            // 64-sample tile
    int tid = threadIdx.x;
    int lx = tid & 31, ly = tid >> 5;
    int col = bx * 32 + lx;

    #pragma unroll
    for (int i = 0; i < 8; i++) {
        int r = ly + i * 8;
        float v = 0.0f;
        if (col < 385) v = inp[(size_t)(by * 64 + r) * 385 + col];
        tile[r][lx] = v;
    }
    __syncthreads();

    int pl = tid & 31;              // sample-pair within tile (0..31)
    int cl = tid >> 5;              // 0..7
    ulonglong2* T2 = reinterpret_cast<ulonglong2*>(g_T2);
    #pragma unroll
    for (int i = 0; i < 2; i++) {
        int cpl = cl + i * 8;       // local col-pair (0..15)
        int c   = cpl * 2;
        int gcp = bx * 16 + cpl;    // global col-pair
        if (gcp < 193) {
            u64 lo = pk2(tile[2 * pl][c],     tile[2 * pl + 1][c]);
            u64 hi = pk2(tile[2 * pl][c + 1], tile[2 * pl + 1][c + 1]);
            T2[(size_t)gcp * np + by * 32 + pl] = make_ulonglong2(lo, hi);
        }
    }
}

// ------------------------------ conv kernel -------------------------------
// Thread pairs (2u, 2u+1) share sample-pair t=u; p=tid&1 selects neuron half
// (L1 neurons 6p..6p+5) and, after the shuffle exchange, the window (A/B).
#define A_W1 0      // 648
#define A_B1 648    // 12
#define A_W2 660    // 144
#define A_B2 804    // 12
#define A_W3 816    // 48
#define A_B3 864    // 4
#define A_N  868

__global__ void __launch_bounds__(128, 5) conv_kernel(
    const float* __restrict__ W1, const float* __restrict__ b1,
    const float* __restrict__ W2, const float* __restrict__ b2,
    const float* __restrict__ W3, const float* __restrict__ b3,
    int np)
{
    __shared__ __align__(16) u64 sw[A_N];
    int tid = threadIdx.x;
    for (int i = tid; i < 648; i += 128) { float v = W1[i]; sw[A_W1+i] = pk2(v,v); }
    for (int i = tid; i < 12;  i += 128) { sw[A_B1+i] = pk2(b1[i],b1[i]);
                                           sw[A_B2+i] = pk2(b2[i],b2[i]); }
    for (int i = tid; i < 144; i += 128) { sw[A_W2+i] = pk2(W2[i],W2[i]); }
    for (int i = tid; i < 48;  i += 128) { sw[A_W3+i] = pk2(W3[i],W3[i]); }
    if (tid < 4) sw[A_B3+tid] = pk2(b3[tid],b3[tid]);
    __syncthreads();

    int gtid = blockIdx.x * 128 + tid;
    int t = gtid >> 1;
    int p = gtid & 1;
    if (t >= np) return;
    int np6 = 6 * p;                 // neuron offset for L1

    const ulonglong2* T2 = reinterpret_cast<const ulonglong2*>(g_T2);

    #pragma unroll 1
    for (int wp = 0; wp < 18; wp++) {
        int x  = wp / 3;
        int yy = (wp - x * 3) * 2;
        int cpb = x * 24 + yy * 3;   // col-pair base

        // L1: 6 neurons (np6..np6+5) for both windows of the pair
        u64 ha[6], hb[6];
        #pragma unroll
        for (int n = 0; n < 6; n++) { ha[n] = sw[A_B1 + np6 + n]; hb[n] = ha[n]; }

        #pragma unroll 1
        for (int ox = 0; ox < 3; ox++) {
            const ulonglong2* g = T2 + (size_t)(cpb + ox * 24) * np + t;
            const u64* wk = sw + A_W1 + ox * 216 + np6;

            // rolling 12-col packed buffer; 6+3+3 LDG.128 per ox
            u64 v[12];
            #pragma unroll
            for (int i = 0; i < 6; i++) {
                ulonglong2 a = __ldg(g + (size_t)i * np);
                v[2*i] = a.x; v[2*i+1] = a.y;
            }
            #pragma unroll
            for (int kk = 0; kk < 6; kk++) {
                u64 va = v[kk], vb = v[kk + 6];
                const ulonglong2* w2 = reinterpret_cast<const ulonglong2*>(wk + kk * 12);
                #pragma unroll
                for (int n2 = 0; n2 < 3; n2++) {
                    ulonglong2 w = w2[n2];
                    ha[2*n2]   = fma2(va, w.x, ha[2*n2]);
                    ha[2*n2+1] = fma2(va, w.y, ha[2*n2+1]);
                    hb[2*n2]   = fma2(vb, w.x, hb[2*n2]);
                    hb[2*n2+1] = fma2(vb, w.y, hb[2*n2+1]);
                }
            }
            #pragma unroll
            for (int i = 0; i < 6; i++) v[i] = v[i + 6];
            #pragma unroll
            for (int i = 0; i < 3; i++) {
                ulonglong2 a = __ldg(g + (size_t)(6 + i) * np);
                v[6+2*i] = a.x; v[7+2*i] = a.y;
            }
            #pragma unroll
            for (int kk = 0; kk < 6; kk++) {
                u64 va = v[kk], vb = v[kk + 6];
                const ulonglong2* w2 = reinterpret_cast<const ulonglong2*>(wk + (6 + kk) * 12);
                #pragma unroll
                for (int n2 = 0; n2 < 3; n2++) {
                    ulonglong2 w = w2[n2];
                    ha[2*n2]   = fma2(va, w.x, ha[2*n2]);
                    ha[2*n2+1] = fma2(va, w.y, ha[2*n2+1]);
                    hb[2*n2]   = fma2(vb, w.x, hb[2*n2]);
                    hb[2*n2+1] = fma2(vb, w.y, hb[2*n2+1]);
                }
            }
            #pragma unroll
            for (int i = 0; i < 6; i++) v[i] = v[i + 6];
            #pragma unroll
            for (int i = 0; i < 3; i++) {
                ulonglong2 a = __ldg(g + (size_t)(9 + i) * np);
                v[6+2*i] = a.x; v[7+2*i] = a.y;
            }
            #pragma unroll
            for (int kk = 0; kk < 6; kk++) {
                u64 va = v[kk], vb = v[kk + 6];
                const ulonglong2* w2 = reinterpret_cast<const ulonglong2*>(wk + (12 + kk) * 12);
                #pragma unroll
                for (int n2 = 0; n2 < 3; n2++) {
                    ulonglong2 w = w2[n2];
                    ha[2*n2]   = fma2(va, w.x, ha[2*n2]);
                    ha[2*n2+1] = fma2(va, w.y, ha[2*n2+1]);
                    hb[2*n2]   = fma2(vb, w.x, hb[2*n2]);
                    hb[2*n2+1] = fma2(vb, w.y, hb[2*n2+1]);
                }
            }
        }
        #pragma unroll
        for (int n = 0; n < 6; n++) { ha[n] = clamp2(ha[n]); hb[n] = clamp2(hb[n]); }

        // exchange: even ends with full winA h[12], odd with full winB h[12]
        u64 h[12];
        #pragma unroll
        for (int i = 0; i < 6; i++) {
            u64 snd = p ? ha[i] : hb[i];
            u64 rcv = shfl_xor64(snd);
            h[i]     = p ? rcv  : ha[i];
            h[6 + i] = p ? hb[i] : rcv;
        }

        // layer 2: 12 -> 12 (one window per thread)
        u64 gg[12];
        #pragma unroll
        for (int n = 0; n < 12; n++) gg[n] = sw[A_B2 + n];
        #pragma unroll 4
        for (int k = 0; k < 12; k++) {
            const ulonglong2* w2 = reinterpret_cast<const ulonglong2*>(sw + A_W2 + k * 12);
            #pragma unroll
            for (int n2 = 0; n2 < 6; n2++) {
                ulonglong2 w = w2[n2];
                gg[2*n2]   = fma2(h[k], w.x, gg[2*n2]);
                gg[2*n2+1] = fma2(h[k], w.y, gg[2*n2+1]);
            }
        }
        #pragma unroll
        for (int n = 0; n < 12; n++) gg[n] = clamp2(gg[n]);

        // layer 3: 12 -> 4
        u64 s[4];
        #pragma unroll
        for (int q = 0; q < 4; q++) s[q] = sw[A_B3 + q];
        #pragma unroll
        for (int k = 0; k < 12; k++) {
            const ulonglong2* w2 = reinterpret_cast<const ulonglong2*>(sw + A_W3 + k * 4);
            ulonglong2 w0 = w2[0];
            ulonglong2 w1 = w2[1];
            s[0] = fma2(gg[k], w0.x, s[0]);
            s[1] = fma2(gg[k], w0.y, s[1]);
            s[2] = fma2(gg[k], w1.x, s[2]);
            s[3] = fma2(gg[k], w1.y, s[3]);
        }
        #pragma unroll
        for (int q = 0; q < 4; q++) s[q] = clamp2(s[q]);

        // store: window index = wa + p; fp16-packed, one 16B store
        int wa = x * 6 + yy;
        uint4 pk;
        pk.x = pair_to_h2(s[0]);
        pk.y = pair_to_h2(s[1]);
        pk.z = pair_to_h2(s[2]);
        pk.w = pair_to_h2(s[3]);
        g_Sh[(size_t)(wa + p) * np + t] = pk;
    }
}

// ------------------------------ head kernel -------------------------------
#define H_V1 0      // 4640 (145x32 dup pairs)
#define H_C1 4640   // 32
#define H_C2 4672   // 32
#define H_V3 4704   // 32
#define H_V2 4736   // 1024 (V2 transposed dup pairs: [j][k])
#define H_C3 5760   // 1 (+1 pad)
#define H_N  5762   // 46096 B

__global__ void __launch_bounds__(128, 4) head_kernel(
    const float* __restrict__ V1, const float* __restrict__ c1,
    const float* __restrict__ V2, const float* __restrict__ c2,
    const float* __restrict__ V3, const float* __restrict__ c3,
    float* __restrict__ out, int np)
{
    __shared__ __align__(16) u64 sv[H_N];
    int tid = threadIdx.x;
    for (int i = tid; i < 4640; i += 128) { float v = V1[i]; sv[H_V1+i] = pk2(v,v); }
    for (int i = tid; i < 32;   i += 128) { sv[H_C1+i] = pk2(c1[i],c1[i]);
                                            sv[H_C2+i] = pk2(c2[i],c2[i]);
                                            sv[H_V3+i] = pk2(V3[i],V3[i]); }
    for (int i = tid; i < 1024; i += 128) { int j = i >> 5, k = i & 31;
                                            float v = V2[k*32 + j]; sv[H_V2+i] = pk2(v,v); }
    if (tid == 0) sv[H_C3] = pk2(c3[0], c3[0]);
    __syncthreads();

    int t = blockIdx.x * 128 + tid;
    if (t >= np) return;

    u64 acc[32];
    #pragma unroll
    for (int j = 0; j < 32; j++) acc[j] = 0ull;

    #pragma unroll 2
    for (int w = 0; w < 36; w++) {
        uint4 sp = __ldg(&g_Sh[(size_t)w * np + t]);
        u64 s0 = h2_to_pair(sp.x);
        u64 s1 = h2_to_pair(sp.y);
        u64 s2 = h2_to_pair(sp.z);
        u64 s3 = h2_to_pair(sp.w);
        const u64* vr = sv + H_V1 + (4 * w) * 32;
        #pragma unroll
        for (int j2 = 0; j2 < 16; j2++) {
            const ulonglong2* w0 = reinterpret_cast<const ulonglong2*>(vr);
            const ulonglong2* w1 = reinterpret_cast<const ulonglong2*>(vr + 32);
            const ulonglong2* w2 = reinterpret_cast<const ulonglong2*>(vr + 64);
            const ulonglong2* w3 = reinterpret_cast<const ulonglong2*>(vr + 96);
            ulonglong2 a = w0[j2], b = w1[j2], c = w2[j2], d = w3[j2];
            acc[2*j2]   = fma2(s0, a.x, acc[2*j2]);
            acc[2*j2+1] = fma2(s0, a.y, acc[2*j2+1]);
            acc[2*j2]   = fma2(s1, b.x, acc[2*j2]);
            acc[2*j2+1] = fma2(s1, b.y, acc[2*j2+1]);
            acc[2*j2]   = fma2(s2, c.x, acc[2*j2]);
            acc[2*j2+1] = fma2(s2, c.y, acc[2*j2+1]);
            acc[2*j2]   = fma2(s3, d.x, acc[2*j2]);
            acc[2*j2+1] = fma2(s3, d.y, acc[2*j2+1]);
        }
    }

    // vision[144] = inp[:,384] (col-pair 192, low element)
    u64 last = g_T2[((size_t)192 * np + t) * 2];
    const u64* v1l = sv + H_V1 + 144 * 32;
    #pragma unroll
    for (int j = 0; j < 32; j++) {
        acc[j] = clamp2(add2(fma2(last, v1l[j], acc[j]), sv[H_C1 + j]));
    }

    // V2 (32->32) + V3 (32->1) fused; V2 stored transposed dup'd pairs
    u64 o = sv[H_C3];
    #pragma unroll 1
    for (int j = 0; j < 32; j++) {
        u64 e = sv[H_C2 + j];
        const ulonglong2* w2 = reinterpret_cast<const ulonglong2*>(sv + H_V2 + j * 32);
        #pragma unroll
        for (int k2 = 0; k2 < 16; k2++) {
            ulonglong2 w = w2[k2];
            e = fma2(acc[2*k2],   w.x, e);
            e = fma2(acc[2*k2+1], w.y, e);
        }
        e = clamp2(e);
        o = fma2(e, sv[H_V3 + j], o);
    }
    o = clamp2(o);

    reinterpret_cast<float2*>(out)[t] = up2(o);
}

extern "C" void kernel_launch(void* const* d_in, const int* in_sizes, int n_in,
                              void* d_out, int out_size) {
    const float* inp = (const float*)d_in[0];
    const float* W1  = (const float*)d_in[1];
    const float* b1  = (const float*)d_in[2];
    const float* W2  = (const float*)d_in[3];
    const float* b2  = (const float*)d_in[4];
    const float* W3  = (const float*)d_in[5];
    const float* b3  = (const float*)d_in[6];
    const float* V1  = (const float*)d_in[7];
    const float* c1  = (const float*)d_in[8];
    const float* V2  = (const float*)d_in[9];
    const float* c2  = (const float*)d_in[10];
    const float* V3  = (const float*)d_in[11];
    const float* c3  = (const float*)d_in[12];

    int B  = in_sizes[0] / 385;   // 131072
    int np = B / 2;               // 65536 sample-pairs

    dim3 tgrid(13, B / 64);
    transpose_kernel<<<tgrid, 256>>>(inp, np);

    int cblocks = (2 * np + 127) / 128;   // 2 threads per sample-pair
    conv_kernel<<<cblocks, 128>>>(W1, b1, W2, b2, W3, b3, np);

    int hblocks = (np + 127) / 128;
    head_kernel<<<hblocks, 128>>>(V1, c1, V2, c2, V3, c3, (float*)d_out, np);
}

// round 17
// speedup vs baseline: 1.1412x; 1.0220x over previous
#include <cuda_runtime.h>
#include <cuda_fp16.h>

typedef unsigned long long u64;

__device__ __forceinline__ u64 pk2(float lo, float hi) {
    u64 r; asm("mov.b64 %0,{%1,%2};" : "=l"(r) : "f"(lo), "f"(hi)); return r;
}
__device__ __forceinline__ float2 up2(u64 v) {
    float2 f; asm("mov.b64 {%0,%1},%2;" : "=f"(f.x), "=f"(f.y) : "l"(v)); return f;
}
__device__ __forceinline__ u64 fma2(u64 a, u64 b, u64 c) {
    u64 d; asm("fma.rn.f32x2 %0,%1,%2,%3;" : "=l"(d) : "l"(a), "l"(b), "l"(c)); return d;
}
__device__ __forceinline__ u64 add2(u64 a, u64 b) {
    u64 d; asm("add.rn.f32x2 %0,%1,%2;" : "=l"(d) : "l"(a), "l"(b)); return d;
}
__device__ __forceinline__ u64 clamp2(u64 v) {
    float2 f = up2(v);
    f.x = fminf(fmaxf(f.x, -1.0f), 1.0f);
    f.y = fminf(fmaxf(f.y, -1.0f), 1.0f);
    return pk2(f.x, f.y);
}
__device__ __forceinline__ u64 shfl_xor64(u64 v) {
    return (u64)__shfl_xor_sync(0xffffffffu, (unsigned long long)v, 1);
}
// u64 packed float pair -> half2 bits (uint)
__device__ __forceinline__ unsigned int pair_to_h2(u64 v) {
    float2 f = up2(v);
    __half2 h = __float22half2_rn(f);
    return *reinterpret_cast<unsigned int*>(&h);
}
// half2 bits -> u64 packed float pair
__device__ __forceinline__ u64 h2_to_pair(unsigned int b) {
    __half2 h = *reinterpret_cast<__half2*>(&b);
    float2 f = __half22float2(h);
    return pk2(f.x, f.y);
}

#define NPMAX 65536
// transposed input (fp16), interleaved col-pairs: pair cp, sample-pair t ->
//   uint2{ h2{inp[2t][2cp],inp[2t+1][2cp]}, h2{...[2cp+1]...} }  (193 pairs)
__device__ uint2 g_T2h[(size_t)193 * NPMAX];    // 101 MB
// sight scratch (fp16): window w (0..35), sample-pair t ->
//   uint4{ h2(sight[4w]), h2(sight[4w+1]), h2(sight[4w+2]), h2(sight[4w+3]) }
__device__ uint4 g_Sh[(size_t)36 * NPMAX];      // 37.7 MB

// ------------------------- transpose + pack kernel -------------------------
__global__ void transpose_kernel(const float* __restrict__ inp, int np)
{
    __shared__ float tile[64][33];
    int bx = blockIdx.x;            // col tile (0..12): cols bx*32..bx*32+31
    int by = blockIdx.y;            // 64-sample tile
    int tid = threadIdx.x;
    int lx = tid & 31, ly = tid >> 5;
    int col = bx * 32 + lx;

    #pragma unroll
    for (int i = 0; i < 8; i++) {
        int r = ly + i * 8;
        float v = 0.0f;
        if (col < 385) v = inp[(size_t)(by * 64 + r) * 385 + col];
        tile[r][lx] = v;
    }
    __syncthreads();

    int pl = tid & 31;              // sample-pair within tile (0..31)
    int cl = tid >> 5;              // 0..7
    #pragma unroll
    for (int i = 0; i < 2; i++) {
        int cpl = cl + i * 8;       // local col-pair (0..15)
        int c   = cpl * 2;
        int gcp = bx * 16 + cpl;    // global col-pair
        if (gcp < 193) {
            __half2 h0 = __floats2half2_rn(tile[2 * pl][c],     tile[2 * pl + 1][c]);
            __half2 h1 = __floats2half2_rn(tile[2 * pl][c + 1], tile[2 * pl + 1][c + 1]);
            uint2 o;
            o.x = *reinterpret_cast<unsigned int*>(&h0);
            o.y = *reinterpret_cast<unsigned int*>(&h1);
            g_T2h[(size_t)gcp * np + by * 32 + pl] = o;
        }
    }
}

// ------------------------------ conv kernel -------------------------------
// Thread pairs (2u, 2u+1) share sample-pair t=u; p=tid&1 selects neuron half
// (L1 neurons 6p..6p+5) and, after the shuffle exchange, the window (A/B).
#define A_W1 0      // 648
#define A_B1 648    // 12
#define A_W2 660    // 144
#define A_B2 804    // 12
#define A_W3 816    // 48
#define A_B3 864    // 4
#define A_N  868

__global__ void __launch_bounds__(128, 5) conv_kernel(
    const float* __restrict__ W1, const float* __restrict__ b1,
    const float* __restrict__ W2, const float* __restrict__ b2,
    const float* __restrict__ W3, const float* __restrict__ b3,
    int np)
{
    __shared__ __align__(16) u64 sw[A_N];
    int tid = threadIdx.x;
    for (int i = tid; i < 648; i += 128) { float v = W1[i]; sw[A_W1+i] = pk2(v,v); }
    for (int i = tid; i < 12;  i += 128) { sw[A_B1+i] = pk2(b1[i],b1[i]);
                                           sw[A_B2+i] = pk2(b2[i],b2[i]); }
    for (int i = tid; i < 144; i += 128) { sw[A_W2+i] = pk2(W2[i],W2[i]); }
    for (int i = tid; i < 48;  i += 128) { sw[A_W3+i] = pk2(W3[i],W3[i]); }
    if (tid < 4) sw[A_B3+tid] = pk2(b3[tid],b3[tid]);
    __syncthreads();

    int gtid = blockIdx.x * 128 + tid;
    int t = gtid >> 1;
    int p = gtid & 1;
    if (t >= np) return;
    int np6 = 6 * p;                 // neuron offset for L1

    #pragma unroll 1
    for (int wp = 0; wp < 18; wp++) {
        int x  = wp / 3;
        int yy = (wp - x * 3) * 2;
        int cpb = x * 24 + yy * 3;   // col-pair base

        // L1: 6 neurons (np6..np6+5) for both windows of the pair
        u64 ha[6], hb[6];
        #pragma unroll
        for (int n = 0; n < 6; n++) { ha[n] = sw[A_B1 + np6 + n]; hb[n] = ha[n]; }

        #pragma unroll 1
        for (int ox = 0; ox < 3; ox++) {
            const uint2* g = g_T2h + (size_t)(cpb + ox * 24) * np + t;
            const u64* wk = sw + A_W1 + ox * 216 + np6;

            // rolling 12-col packed buffer; 6+3+3 LDG.64 per ox (fp16 -> f32)
            u64 v[12];
            #pragma unroll
            for (int i = 0; i < 6; i++) {
                uint2 a = __ldg(g + (size_t)i * np);
                v[2*i] = h2_to_pair(a.x); v[2*i+1] = h2_to_pair(a.y);
            }
            #pragma unroll
            for (int kk = 0; kk < 6; kk++) {
                u64 va = v[kk], vb = v[kk + 6];
                const ulonglong2* w2 = reinterpret_cast<const ulonglong2*>(wk + kk * 12);
                #pragma unroll
                for (int n2 = 0; n2 < 3; n2++) {
                    ulonglong2 w = w2[n2];
                    ha[2*n2]   = fma2(va, w.x, ha[2*n2]);
                    ha[2*n2+1] = fma2(va, w.y, ha[2*n2+1]);
                    hb[2*n2]   = fma2(vb, w.x, hb[2*n2]);
                    hb[2*n2+1] = fma2(vb, w.y, hb[2*n2+1]);
                }
            }
            #pragma unroll
            for (int i = 0; i < 6; i++) v[i] = v[i + 6];
            #pragma unroll
            for (int i = 0; i < 3; i++) {
                uint2 a = __ldg(g + (size_t)(6 + i) * np);
                v[6+2*i] = h2_to_pair(a.x); v[7+2*i] = h2_to_pair(a.y);
            }
            #pragma unroll
            for (int kk = 0; kk < 6; kk++) {
                u64 va = v[kk], vb = v[kk + 6];
                const ulonglong2* w2 = reinterpret_cast<const ulonglong2*>(wk + (6 + kk) * 12);
                #pragma unroll
                for (int n2 = 0; n2 < 3; n2++) {
                    ulonglong2 w = w2[n2];
                    ha[2*n2]   = fma2(va, w.x, ha[2*n2]);
                    ha[2*n2+1] = fma2(va, w.y, ha[2*n2+1]);
                    hb[2*n2]   = fma2(vb, w.x, hb[2*n2]);
                    hb[2*n2+1] = fma2(vb, w.y, hb[2*n2+1]);
                }
            }
            #pragma unroll
            for (int i = 0; i < 6; i++) v[i] = v[i + 6];
            #pragma unroll
            for (int i = 0; i < 3; i++) {
                uint2 a = __ldg(g + (size_t)(9 + i) * np);
                v[6+2*i] = h2_to_pair(a.x); v[7+2*i] = h2_to_pair(a.y);
            }
            #pragma unroll
            for (int kk = 0; kk < 6; kk++) {
                u64 va = v[kk], vb = v[kk + 6];
                const ulonglong2* w2 = reinterpret_cast<const ulonglong2*>(wk + (12 + kk) * 12);
                #pragma unroll
                for (int n2 = 0; n2 < 3; n2++) {
                    ulonglong2 w = w2[n2];
                    ha[2*n2]   = fma2(va, w.x, ha[2*n2]);
                    ha[2*n2+1] = fma2(va, w.y, ha[2*n2+1]);
                    hb[2*n2]   = fma2(vb, w.x, hb[2*n2]);
                    hb[2*n2+1] = fma2(vb, w.y, hb[2*n2+1]);
                }
            }
        }
        #pragma unroll
        for (int n = 0; n < 6; n++) { ha[n] = clamp2(ha[n]); hb[n] = clamp2(hb[n]); }

        // exchange: even ends with full winA h[12], odd with full winB h[12]
        u64 h[12];
        #pragma unroll
        for (int i = 0; i < 6; i++) {
            u64 snd = p ? ha[i] : hb[i];
            u64 rcv = shfl_xor64(snd);
            h[i]     = p ? rcv  : ha[i];
            h[6 + i] = p ? hb[i] : rcv;
        }

        // layer 2: 12 -> 12 (one window per thread)
        u64 gg[12];
        #pragma unroll
        for (int n = 0; n < 12; n++) gg[n] = sw[A_B2 + n];
        #pragma unroll 4
        for (int k = 0; k < 12; k++) {
            const ulonglong2* w2 = reinterpret_cast<const ulonglong2*>(sw + A_W2 + k * 12);
            #pragma unroll
            for (int n2 = 0; n2 < 6; n2++) {
                ulonglong2 w = w2[n2];
                gg[2*n2]   = fma2(h[k], w.x, gg[2*n2]);
                gg[2*n2+1] = fma2(h[k], w.y, gg[2*n2+1]);
            }
        }
        #pragma unroll
        for (int n = 0; n < 12; n++) gg[n] = clamp2(gg[n]);

        // layer 3: 12 -> 4
        u64 s[4];
        #pragma unroll
        for (int q = 0; q < 4; q++) s[q] = sw[A_B3 + q];
        #pragma unroll
        for (int k = 0; k < 12; k++) {
            const ulonglong2* w2 = reinterpret_cast<const ulonglong2*>(sw + A_W3 + k * 4);
            ulonglong2 w0 = w2[0];
            ulonglong2 w1 = w2[1];
            s[0] = fma2(gg[k], w0.x, s[0]);
            s[1] = fma2(gg[k], w0.y, s[1]);
            s[2] = fma2(gg[k], w1.x, s[2]);
            s[3] = fma2(gg[k], w1.y, s[3]);
        }
        #pragma unroll
        for (int q = 0; q < 4; q++) s[q] = clamp2(s[q]);

        // store: window index = wa + p; fp16-packed, one 16B store
        int wa = x * 6 + yy;
        uint4 pk;
        pk.x = pair_to_h2(s[0]);
        pk.y = pair_to_h2(s[1]);
        pk.z = pair_to_h2(s[2]);
        pk.w = pair_to_h2(s[3]);
        g_Sh[(size_t)(wa + p) * np + t] = pk;
    }
}

// ------------------------------ head kernel -------------------------------
#define H_V1 0      // 4640 (145x32 dup pairs)
#define H_C1 4640   // 32
#define H_C2 4672   // 32
#define H_V3 4704   // 32
#define H_V2 4736   // 1024 (V2 transposed dup pairs: [j][k])
#define H_C3 5760   // 1 (+1 pad)
#define H_N  5762   // 46096 B

__global__ void __launch_bounds__(128, 5) head_kernel(
    const float* __restrict__ V1, const float* __restrict__ c1,
    const float* __restrict__ V2, const float* __restrict__ c2,
    const float* __restrict__ V3, const float* __restrict__ c3,
    float* __restrict__ out, int np)
{
    __shared__ __align__(16) u64 sv[H_N];
    int tid = threadIdx.x;
    for (int i = tid; i < 4640; i += 128) { float v = V1[i]; sv[H_V1+i] = pk2(v,v); }
    for (int i = tid; i < 32;   i += 128) { sv[H_C1+i] = pk2(c1[i],c1[i]);
                                            sv[H_C2+i] = pk2(c2[i],c2[i]);
                                            sv[H_V3+i] = pk2(V3[i],V3[i]); }
    for (int i = tid; i < 1024; i += 128) { int j = i >> 5, k = i & 31;
                                            float v = V2[k*32 + j]; sv[H_V2+i] = pk2(v,v); }
    if (tid == 0) sv[H_C3] = pk2(c3[0], c3[0]);
    __syncthreads();

    int t = blockIdx.x * 128 + tid;
    if (t >= np) return;

    u64 acc[32];
    #pragma unroll
    for (int j = 0; j < 32; j++) acc[j] = 0ull;

    #pragma unroll 2
    for (int w = 0; w < 36; w++) {
        uint4 sp = __ldg(&g_Sh[(size_t)w * np + t]);
        u64 s0 = h2_to_pair(sp.x);
        u64 s1 = h2_to_pair(sp.y);
        u64 s2 = h2_to_pair(sp.z);
        u64 s3 = h2_to_pair(sp.w);
        const u64* vr = sv + H_V1 + (4 * w) * 32;
        #pragma unroll
        for (int j2 = 0; j2 < 16; j2++) {
            const ulonglong2* w0 = reinterpret_cast<const ulonglong2*>(vr);
            const ulonglong2* w1 = reinterpret_cast<const ulonglong2*>(vr + 32);
            const ulonglong2* w2 = reinterpret_cast<const ulonglong2*>(vr + 64);
            const ulonglong2* w3 = reinterpret_cast<const ulonglong2*>(vr + 96);
            ulonglong2 a = w0[j2], b = w1[j2], c = w2[j2], d = w3[j2];
            acc[2*j2]   = fma2(s0, a.x, acc[2*j2]);
            acc[2*j2+1] = fma2(s0, a.y, acc[2*j2+1]);
            acc[2*j2]   = fma2(s1, b.x, acc[2*j2]);
            acc[2*j2+1] = fma2(s1, b.y, acc[2*j2+1]);
            acc[2*j2]   = fma2(s2, c.x, acc[2*j2]);
            acc[2*j2+1] = fma2(s2, c.y, acc[2*j2+1]);
            acc[2*j2]   = fma2(s3, d.x, acc[2*j2]);
            acc[2*j2+1] = fma2(s3, d.y, acc[2*j2+1]);
        }
    }

    // vision[144] = inp[:,384] (col-pair 192, low half2)
    uint2 lq = __ldg(&g_T2h[(size_t)192 * np + t]);
    u64 last = h2_to_pair(lq.x);
    const u64* v1l = sv + H_V1 + 144 * 32;
    #pragma unroll
    for (int j = 0; j < 32; j++) {
        acc[j] = clamp2(add2(fma2(last, v1l[j], acc[j]), sv[H_C1 + j]));
    }

    // V2 (32->32) + V3 (32->1) fused; V2 stored transposed dup'd pairs
    u64 o = sv[H_C3];
    #pragma unroll 1
    for (int j = 0; j < 32; j++) {
        u64 e = sv[H_C2 + j];
        const ulonglong2* w2 = reinterpret_cast<const ulonglong2*>(sv + H_V2 + j * 32);
        #pragma unroll
        for (int k2 = 0; k2 < 16; k2++) {
            ulonglong2 w = w2[k2];
            e = fma2(acc[2*k2],   w.x, e);
            e = fma2(acc[2*k2+1], w.y, e);
        }
        e = clamp2(e);
        o = fma2(e, sv[H_V3 + j], o);
    }
    o = clamp2(o);

    reinterpret_cast<float2*>(out)[t] = up2(o);
}

extern "C" void kernel_launch(void* const* d_in, const int* in_sizes, int n_in,
                              void* d_out, int out_size) {
    const float* inp = (const float*)d_in[0];
    const float* W1  = (const float*)d_in[1];
    const float* b1  = (const float*)d_in[2];
    const float* W2  = (const float*)d_in[3];
    const float* b2  = (const float*)d_in[4];
    const float* W3  = (const float*)d_in[5];
    const float* b3  = (const float*)d_in[6];
    const float* V1  = (const float*)d_in[7];
    const float* c1  = (const float*)d_in[8];
    const float* V2  = (const float*)d_in[9];
    const float* c2  = (const float*)d_in[10];
    const float* V3  = (const float*)d_in[11];
    const float* c3  = (const float*)d_in[12];

    int B  = in_sizes[0] / 385;   // 131072
    int np = B / 2;               // 65536 sample-pairs

    dim3 tgrid(13, B / 64);
    transpose_kernel<<<tgrid, 256>>>(inp, np);

    int cblocks = (2 * np + 127) / 128;   // 2 threads per sample-pair
    conv_kernel<<<cblocks, 128>>>(W1, b1, W2, b2, W3, b3, np);

    int hblocks = (np + 127) / 128;
    head_kernel<<<hblocks, 128>>>(V1, c1, V2, c2, V3, c3, (float*)d_out, np);
}